// round 15
// baseline (speedup 1.0000x reference)
#include <cuda_runtime.h>
#include <cuda_bf16.h>
#include <cuda_fp16.h>
#include <math.h>

// ---------------------------------------------------------------------------
// LSTM: S=512, B=64, I=256, H=512
// out = [h_seq (S,B,H) | h_final (B,H) | c_final (B,H)]  (fp32)
// xproj + recurrence both on mma.sync m16n8k16 (hi/lo fp16 splits ~ fp32).
// R15: rec partition 16bg x 8ug, 512 thr -> 8-arrival barriers, 8KB staging.
// ---------------------------------------------------------------------------

#define S_LEN 512
#define BATCH 64
#define IN_DIM 256
#define HID 512
#define G4 2048              // 4*H
#define BH (BATCH*HID)       // 32768
#define BG (BATCH*G4)        // 131072
#define NCTA 128
#define BST 520              // rec B smem row stride (halves)

// xproj tiling: 64x128 CTA tile, warp tile 32x32, 2 CTAs/SM
#define XM 64
#define XN 128
#define XBK 32
#define XST 40               // xproj smem row stride (halves): 20 words/row
#define XA_BUF (XM*XST)      // 2560 halves per A buffer
#define XB_BUF (XN*XST)      // 5120 halves per B buffer
#define XP_SMEM ((4*XA_BUF + 2*XB_BUF) * 2)   // 40960 bytes

// -------------------- device scratch (static: no allocs allowed) ------------
__device__ float  g_xp[(size_t)S_LEN * BATCH * G4];  // x@Wx + bx + bh
__device__ __half g_WxT[(size_t)G4 * IN_DIM];        // WxT[n][k] fp16
__device__ float  g_WhT[(size_t)G4 * HID];           // WhT[col][k]
__device__ float  g_bias[G4];                        // bx + bh
__device__ __half g_hh[2][BH];                       // h hi fp16, ping-pong
__device__ __half g_hl[2][BH];                       // h lo fp16, ping-pong
__device__ unsigned int g_barc[16 * 16];             // per-bg counters, 64B apart

// fast activations
__device__ __forceinline__ float fast_exp(float x) {
    float e;
    asm("ex2.approx.f32 %0, %1;" : "=f"(e) : "f"(x * 1.4426950408889634f));
    return e;
}
__device__ __forceinline__ float fast_rcp(float x) {
    float r;
    asm("rcp.approx.f32 %0, %1;" : "=f"(r) : "f"(x));
    return r;
}
__device__ __forceinline__ float fast_sigmoid(float x) {
    return fast_rcp(1.f + fast_exp(-x));
}
__device__ __forceinline__ float fast_tanh(float x) {
    return 2.f * fast_rcp(1.f + fast_exp(-2.f * x)) - 1.f;
}

__device__ __forceinline__ void cpasync16(unsigned dst, const void* src) {
    asm volatile("cp.async.cg.shared.global [%0], [%1], 16;"
                 :: "r"(dst), "l"(src));
}

// mma.sync m16n8k16 row.col f32.f16.f16.f32 (accumulate in place)
__device__ __forceinline__ void hmma16816(float& d0, float& d1, float& d2, float& d3,
                                          unsigned a0, unsigned a1, unsigned a2, unsigned a3,
                                          unsigned b0, unsigned b1) {
    asm volatile(
        "mma.sync.aligned.m16n8k16.row.col.f32.f16.f16.f32 "
        "{%0,%1,%2,%3}, {%4,%5,%6,%7}, {%8,%9}, {%0,%1,%2,%3};"
        : "+f"(d0), "+f"(d1), "+f"(d2), "+f"(d3)
        : "r"(a0), "r"(a1), "r"(a2), "r"(a3), "r"(b0), "r"(b1));
}

// -------------------- merged prep kernel --------------------------------------
__global__ void prep_kernel(
    const float* __restrict__ Wxf, const float* __restrict__ Wxi,
    const float* __restrict__ Wxo, const float* __restrict__ Wxg,
    const float* __restrict__ Whf, const float* __restrict__ Whi,
    const float* __restrict__ Who, const float* __restrict__ Whg,
    const float* __restrict__ bxf, const float* __restrict__ bhf,
    const float* __restrict__ bxi, const float* __restrict__ bhi,
    const float* __restrict__ bxo, const float* __restrict__ bho,
    const float* __restrict__ bxg, const float* __restrict__ bhg)
{
    int idx = blockIdx.x * blockDim.x + threadIdx.x;

    if (idx < 16 * 16) g_barc[idx] = 0u;

    if (idx < G4) {
        int g = idx >> 9, jj = idx & 511;
        const float* bx = (g == 0) ? bxf : (g == 1) ? bxi : (g == 2) ? bxo : bxg;
        const float* bh = (g == 0) ? bhf : (g == 1) ? bhi : (g == 2) ? bho : bhg;
        g_bias[idx] = bx[jj] + bh[jj];
    }

    if (idx < G4 * IN_DIM) {         // g_WxT[n][k] = Wx_gate[k][unit] fp16
        int n = idx >> 8;
        int k = idx & 255;
        int g = n >> 9, unit = n & 511;
        const float* W = (g == 0) ? Wxf : (g == 1) ? Wxi : (g == 2) ? Wxo : Wxg;
        g_WxT[idx] = __float2half_rn(W[k * HID + unit]);
    }

    if (idx < G4 * HID) {
        int col = idx >> 9;
        int k   = idx & 511;
        int g   = col >> 9;
        int jj  = col & 511;
        const float* W = (g == 0) ? Whf : (g == 1) ? Whi : (g == 2) ? Who : Whg;
        g_WhT[idx] = W[k * HID + jj];   // WhT[col][k] = Wh[k][col]
    }
}

// -------------------- xproj via mma.sync (unchanged R12) -----------------------
__global__ __launch_bounds__(256, 2) void xproj_hmma(const float* __restrict__ x)
{
    extern __shared__ __half xs[];
    __half* a_hi = xs;                       // 2 x XA_BUF
    __half* a_lo = xs + 2 * XA_BUF;          // 2 x XA_BUF
    __half* bsm  = xs + 4 * XA_BUF;          // 2 x XB_BUF

    const int tid  = threadIdx.x;
    const int w    = tid >> 5;
    const int lane = tid & 31;
    const int g    = lane >> 2;
    const int tq   = lane & 3;
    const int mw   = w >> 2;                 // 0..1
    const int nw   = w & 3;                  // 0..3
    const int bm   = blockIdx.y * XM;
    const int bn   = blockIdx.x * XN;

    const int arow = tid >> 2;               // 0..63
    const int aq   = tid & 3;                // k-chunk of 8 floats
    const float* axp = x + (size_t)(bm + arow) * IN_DIM + aq * 8;

    const unsigned sb   = (unsigned)__cvta_generic_to_shared(xs);
    const unsigned bsmb = sb + (unsigned)(4 * XA_BUF) * 2u;

    float acc[2][4][4];
#pragma unroll
    for (int f = 0; f < 2; f++)
#pragma unroll
        for (int nf = 0; nf < 4; nf++)
#pragma unroll
            for (int q = 0; q < 4; q++) acc[f][nf][q] = 0.f;

#define CPB(p, ktg)                                                          \
    do {                                                                     \
        _Pragma("unroll")                                                    \
        for (int i = 0; i < 2; i++) {                                        \
            int idx = tid + (i << 8);                                        \
            int n   = idx >> 2;                                              \
            int ko  = (idx & 3) << 3;                                        \
            unsigned dst = bsmb + (unsigned)((p) * XB_BUF + n * XST + ko) * 2u; \
            cpasync16(dst, (const void*)(g_WxT + (size_t)(bn + n) * IN_DIM + (ktg) + ko)); \
        }                                                                    \
    } while (0)

#define STAGEA(p, v0, v1)                                                    \
    do {                                                                     \
        float ff[8] = {v0.x, v0.y, v0.z, v0.w, v1.x, v1.y, v1.z, v1.w};      \
        __align__(16) __half hh[8];                                          \
        __align__(16) __half hl[8];                                          \
        _Pragma("unroll")                                                    \
        for (int i = 0; i < 8; i++) {                                        \
            hh[i] = __float2half_rn(ff[i]);                                  \
            hl[i] = __float2half_rn(ff[i] - __half2float(hh[i]));            \
        }                                                                    \
        *(uint4*)(a_hi + (p) * XA_BUF + arow * XST + aq * 8) = *(uint4*)hh;  \
        *(uint4*)(a_lo + (p) * XA_BUF + arow * XST + aq * 8) = *(uint4*)hl;  \
    } while (0)

    // ---- prologue: tile 0 ----
    {
        CPB(0, 0);
        asm volatile("cp.async.commit_group;");
        float4 v0 = *(const float4*)(axp);
        float4 v1 = *(const float4*)(axp + 4);
        STAGEA(0, v0, v1);
        asm volatile("cp.async.wait_group 0;" ::: "memory");
    }
    __syncthreads();

#pragma unroll
    for (int kt = 0; kt < IN_DIM / XBK; kt++) {
        const int p = kt & 1;
        const bool has_next = (kt + 1) < (IN_DIM / XBK);

        float4 nv0, nv1;
        if (has_next) {
            CPB(p ^ 1, (kt + 1) * XBK);
            asm volatile("cp.async.commit_group;");
            nv0 = *(const float4*)(axp + (kt + 1) * XBK);
            nv1 = *(const float4*)(axp + (kt + 1) * XBK + 4);
        }

        const __half* ah_p = a_hi + p * XA_BUF;
        const __half* al_p = a_lo + p * XA_BUF;
        const __half* b_p  = bsm + p * XB_BUF;

#pragma unroll
        for (int ks = 0; ks < 2; ks++) {
            unsigned AH[2][4], AL[2][4], BB[4][2];
#pragma unroll
            for (int f = 0; f < 2; f++)
#pragma unroll
                for (int j = 0; j < 4; j++) {
                    int row = mw * 32 + f * 16 + g + ((j & 1) << 3);
                    int k   = ks * 16 + tq * 2 + ((j >> 1) << 3);
                    AH[f][j] = *(const unsigned*)(ah_p + row * XST + k);
                    AL[f][j] = *(const unsigned*)(al_p + row * XST + k);
                }
#pragma unroll
            for (int nf = 0; nf < 4; nf++) {
                int n = nw * 32 + nf * 8 + g;
                BB[nf][0] = *(const unsigned*)(b_p + n * XST + ks * 16 + tq * 2);
                BB[nf][1] = *(const unsigned*)(b_p + n * XST + ks * 16 + tq * 2 + 8);
            }
#pragma unroll
            for (int f = 0; f < 2; f++)
#pragma unroll
                for (int nf = 0; nf < 4; nf++) {
                    hmma16816(acc[f][nf][0], acc[f][nf][1], acc[f][nf][2], acc[f][nf][3],
                              AH[f][0], AH[f][1], AH[f][2], AH[f][3],
                              BB[nf][0], BB[nf][1]);
                    hmma16816(acc[f][nf][0], acc[f][nf][1], acc[f][nf][2], acc[f][nf][3],
                              AL[f][0], AL[f][1], AL[f][2], AL[f][3],
                              BB[nf][0], BB[nf][1]);
                }
        }

        if (has_next) {
            STAGEA(p ^ 1, nv0, nv1);
            asm volatile("cp.async.wait_group 0;" ::: "memory");
            __syncthreads();
        }
    }

    // ---- epilogue: bias add + store ----
#pragma unroll
    for (int nf = 0; nf < 4; nf++) {
        int col = bn + nw * 32 + nf * 8 + tq * 2;
        float b0 = g_bias[col];
        float b1 = g_bias[col + 1];
#pragma unroll
        for (int f = 0; f < 2; f++) {
            int r0 = bm + mw * 32 + f * 16 + g;
            float2 o0 = make_float2(acc[f][nf][0] + b0, acc[f][nf][1] + b1);
            float2 o1 = make_float2(acc[f][nf][2] + b0, acc[f][nf][3] + b1);
            *(float2*)&g_xp[(size_t)r0 * G4 + col]       = o0;
            *(float2*)&g_xp[(size_t)(r0 + 8) * G4 + col] = o1;
        }
    }
#undef CPB
#undef STAGEA
}

// -------------------- recurrence: mma.sync persistent --------------------------
// R15: 128 CTAs = 16 bg (4 batches) x 8 ug (64 units). 512 threads = 16 warps.
// D[256 gate-rows, 8 cols (4 real batches)] = Wh_slice[256 x 512] * h^T.
// Warp w = m-tile (rows w*16..+15). Gate-row r = gate*64 + unit.
// B rows 4..7 are zero (padding). Barrier: per-bg counter, 8 arrivals.
// Staging: 4 batches hi+lo = 8KB.
__global__ __launch_bounds__(512, 1) void lstm_rec_kernel(float* __restrict__ out)
{
    __shared__ __align__(16) __half b_hi[8 * BST];
    __shared__ __align__(16) __half b_lo[8 * BST];
    __shared__ float rg[256 * 9];

    const int tid  = threadIdx.x;
    const int w    = tid >> 5;
    const int lane = tid & 31;
    const int g    = lane >> 2;
    const int tq   = lane & 3;
    const int mt   = w;                 // 0..15 (rows mt*16..+15)
    const int cta  = blockIdx.x;
    const int ug   = cta & 7;           // units [ug*64, +64)
    const int bg   = cta >> 3;          // batches [bg*4, +4)

    // ---- zero padding rows 4..7 of B tiles (once) ----
    for (int i = tid; i < 4 * BST; i += 512) {
        b_hi[4 * BST + i] = __float2half(0.f);
        b_lo[4 * BST + i] = __float2half(0.f);
    }

    // ---- Wh A-fragments (registers, once) ----
    unsigned ar[32][4];
#pragma unroll
    for (int ks = 0; ks < 32; ks++) {
#pragma unroll
        for (int j = 0; j < 4; j++) {
            int row  = mt * 16 + g + ((j & 1) << 3);     // 0..255
            int k    = ks * 16 + tq * 2 + ((j >> 1) << 3);
            int wcol = (row >> 6) * HID + (ug << 6) + (row & 63);
            float v0 = g_WhT[(size_t)wcol * HID + k];
            float v1 = g_WhT[(size_t)wcol * HID + k + 1];
            __half2 hv = __floats2half2_rn(v0, v1);
            ar[ks][j] = *(unsigned*)&hv;
        }
    }

    // B frag pointers: n-row = g (0..7; rows 4..7 zero)
    const __half* bhr = b_hi + g * BST + tq * 2;
    const __half* blr = b_lo + g * BST + tq * 2;

    const unsigned shi = (unsigned)__cvta_generic_to_shared(b_hi);
    const unsigned slo = (unsigned)__cvta_generic_to_shared(b_lo);

    // ---- activation mapping (tid < 256): ab 0..3, au 0..63 ----
    const int ab = tid >> 6;
    const int au = tid & 63;
    const int gb = bg * 4 + ab;
    const int gj = (ug << 6) + au;
    const bool is_act = (tid < 256);

    unsigned int* barp = &g_barc[bg * 16];

    const size_t xof = (size_t)gb * G4 + gj;
    float c0 = 0.f, c1 = 0.f, c2 = 0.f, c3 = 0.f;
    if (is_act) {
        c0 = g_xp[xof];
        c1 = g_xp[xof + 512];
        c2 = g_xp[xof + 1024];
        c3 = g_xp[xof + 1536];
    }

    float cval = 0.f;
    __syncthreads();    // padding zeros + A-frags visible

    for (int t = 0; t < S_LEN; t++) {
        if (t > 0) {
            // ---- stage h(t-1) hi/lo: 4 rows x 512 halves each = 8KB ----
            const int pp = (t - 1) & 1;
            const __half* s_hi = g_hh[pp] + (size_t)(bg * 4) * HID;
            const __half* s_lo = g_hl[pp] + (size_t)(bg * 4) * HID;
            {
                int idx  = tid;                      // 512 chunks / 512 thr
                int buf  = idx >> 8;                 // 0: hi, 1: lo
                int rem  = idx & 255;
                int lrow = rem >> 6;                 // 0..3
                int ch   = rem & 63;
                const __half* src = (buf ? s_lo : s_hi) + lrow * HID + (ch << 3);
                unsigned dst = (buf ? slo : shi)
                               + (unsigned)(lrow * BST + (ch << 3)) * 2u;
                cpasync16(dst, (const void*)src);
            }
            asm volatile("cp.async.commit_group;");
            asm volatile("cp.async.wait_group 0;" ::: "memory");
            __syncthreads();
        }

        // prefetch xp(t+1)
        float n0 = 0.f, n1 = 0.f, n2 = 0.f, n3 = 0.f;
        if (is_act && (t + 1 < S_LEN)) {
            size_t nb = (size_t)(t + 1) * BG + xof;
            n0 = g_xp[nb]; n1 = g_xp[nb + 512];
            n2 = g_xp[nb + 1024]; n3 = g_xp[nb + 1536];
        }

        if (t > 0) {
            float d0 = 0.f, d1 = 0.f, d2 = 0.f, d3 = 0.f;
#pragma unroll
            for (int ks = 0; ks < 32; ks++) {
                unsigned b0h = *(const unsigned*)(bhr + ks * 16);
                unsigned b1h = *(const unsigned*)(bhr + ks * 16 + 8);
                unsigned b0l = *(const unsigned*)(blr + ks * 16);
                unsigned b1l = *(const unsigned*)(blr + ks * 16 + 8);
                hmma16816(d0, d1, d2, d3,
                          ar[ks][0], ar[ks][1], ar[ks][2], ar[ks][3], b0h, b1h);
                hmma16816(d0, d1, d2, d3,
                          ar[ks][0], ar[ks][1], ar[ks][2], ar[ks][3], b0l, b1l);
            }
            // D frag -> rg (cols 0..3 real; tq>=2 lanes hold zero cols, store ok)
            int row = mt * 16 + g;
            int col = tq * 2;
            rg[row * 9 + col]           = d0;
            rg[row * 9 + col + 1]       = d1;
            rg[(row + 8) * 9 + col]     = d2;
            rg[(row + 8) * 9 + col + 1] = d3;
            __syncthreads();
        }

        // ---- activation: thread (ab, au), tid<256 ----
        float hval = 0.f;
        if (is_act) {
            float gf = c0, gi = c1, go = c2, gg = c3;
            if (t > 0) {
                gf += rg[(au +   0) * 9 + ab];
                gi += rg[(au +  64) * 9 + ab];
                go += rg[(au + 128) * 9 + ab];
                gg += rg[(au + 192) * 9 + ab];
            }
            c0 = n0; c1 = n1; c2 = n2; c3 = n3;

            float fg = fast_sigmoid(gf);
            float ig = fast_sigmoid(gi);
            float og = fast_sigmoid(go);
            float gt = fast_tanh(gg);
            cval = fg * cval + ig * gt;
            hval = og * fast_tanh(cval);

            out[(size_t)t * BH + (size_t)gb * HID + gj] = hval;
            if (t + 1 < S_LEN) {
                const int p = t & 1;
                __half hi = __float2half_rn(hval);
                __half lo = __float2half_rn(hval - __half2float(hi));
                g_hh[p][(size_t)gb * HID + gj] = hi;
                g_hl[p][(size_t)gb * HID + gj] = lo;
            }
        }

        if (t < S_LEN - 1) {
            // ---- per-bg barrier: 8 arrivals ----
            __syncthreads();
            if (tid == 0) {
                asm volatile("red.release.gpu.global.add.u32 [%0], 1;"
                             :: "l"(barp) : "memory");
                unsigned target = (unsigned)(t + 1) * 8u;
                unsigned v;
                while (true) {
                    asm volatile("ld.acquire.gpu.global.u32 %0, [%1];"
                                 : "=r"(v) : "l"(barp) : "memory");
                    if (v >= target) break;
                    __nanosleep(20);
                }
            }
            __syncthreads();
        } else if (is_act) {
            out[(size_t)S_LEN * BH + (size_t)gb * HID + gj] = hval;        // h_f
            out[(size_t)S_LEN * BH + BH + (size_t)gb * HID + gj] = cval;   // c_f
        }
    }
}

// -------------------- launch ------------------------------------------------
extern "C" void kernel_launch(void* const* d_in, const int* in_sizes, int n_in,
                              void* d_out, int out_size)
{
    (void)in_sizes; (void)n_in; (void)out_size;
    const float* x   = (const float*)d_in[0];
    const float* Wxf = (const float*)d_in[1];
    const float* bxf = (const float*)d_in[2];
    const float* Whf = (const float*)d_in[3];
    const float* bhf = (const float*)d_in[4];
    const float* Wxi = (const float*)d_in[5];
    const float* bxi = (const float*)d_in[6];
    const float* Whi = (const float*)d_in[7];
    const float* bhi = (const float*)d_in[8];
    const float* Wxo = (const float*)d_in[9];
    const float* bxo = (const float*)d_in[10];
    const float* Who = (const float*)d_in[11];
    const float* bho = (const float*)d_in[12];
    const float* Wxg = (const float*)d_in[13];
    const float* bxg = (const float*)d_in[14];
    const float* Whg = (const float*)d_in[15];
    const float* bhg = (const float*)d_in[16];
    float* out = (float*)d_out;

    prep_kernel<<<(G4 * HID + 255) / 256, 256>>>(
        Wxf, Wxi, Wxo, Wxg, Whf, Whi, Who, Whg,
        bxf, bhf, bxi, bhi, bxo, bho, bxg, bhg);

    static bool attr_set = false;
    if (!attr_set) {
        cudaFuncSetAttribute(xproj_hmma,
                             cudaFuncAttributeMaxDynamicSharedMemorySize, XP_SMEM);
        attr_set = true;
    }
    dim3 gproj(G4 / XN, (S_LEN * BATCH) / XM);
    xproj_hmma<<<gproj, 256, XP_SMEM>>>(x);

    lstm_rec_kernel<<<NCTA, 512>>>(out);
}

// round 16
// speedup vs baseline: 1.4057x; 1.4057x over previous
#include <cuda_runtime.h>
#include <cuda_bf16.h>
#include <cuda_fp16.h>
#include <math.h>

// ---------------------------------------------------------------------------
// LSTM: S=512, B=64, I=256, H=512
// out = [h_seq (S,B,H) | h_final (B,H) | c_final (B,H)]  (fp32)
// xproj + recurrence both on mma.sync m16n8k16 (hi/lo fp16 splits ~ fp32).
// R16 = R14 (8bg x 16ug, 256 thr) + distributed-flag barrier (no atomic RMW).
// ---------------------------------------------------------------------------

#define S_LEN 512
#define BATCH 64
#define IN_DIM 256
#define HID 512
#define G4 2048              // 4*H
#define BH (BATCH*HID)       // 32768
#define BG (BATCH*G4)        // 131072
#define NCTA 128
#define BST 520              // rec B smem row stride (halves)

// xproj tiling: 64x128 CTA tile, warp tile 32x32, 2 CTAs/SM
#define XM 64
#define XN 128
#define XBK 32
#define XST 40               // xproj smem row stride (halves): 20 words/row
#define XA_BUF (XM*XST)      // 2560 halves per A buffer
#define XB_BUF (XN*XST)      // 5120 halves per B buffer
#define XP_SMEM ((4*XA_BUF + 2*XB_BUF) * 2)   // 40960 bytes

// -------------------- device scratch (static: no allocs allowed) ------------
__device__ float  g_xp[(size_t)S_LEN * BATCH * G4];  // x@Wx + bx + bh
__device__ __half g_WxT[(size_t)G4 * IN_DIM];        // WxT[n][k] fp16
__device__ float  g_WhT[(size_t)G4 * HID];           // WhT[col][k]
__device__ float  g_bias[G4];                        // bx + bh
__device__ __half g_hh[2][BH];                       // h hi fp16, ping-pong
__device__ __half g_hl[2][BH];                       // h lo fp16, ping-pong
__device__ unsigned int g_flags[8 * 16 * 16];        // [bg][ug] flags, 64B apart

// fast activations
__device__ __forceinline__ float fast_exp(float x) {
    float e;
    asm("ex2.approx.f32 %0, %1;" : "=f"(e) : "f"(x * 1.4426950408889634f));
    return e;
}
__device__ __forceinline__ float fast_rcp(float x) {
    float r;
    asm("rcp.approx.f32 %0, %1;" : "=f"(r) : "f"(x));
    return r;
}
__device__ __forceinline__ float fast_sigmoid(float x) {
    return fast_rcp(1.f + fast_exp(-x));
}
__device__ __forceinline__ float fast_tanh(float x) {
    return 2.f * fast_rcp(1.f + fast_exp(-2.f * x)) - 1.f;
}

__device__ __forceinline__ void cpasync16(unsigned dst, const void* src) {
    asm volatile("cp.async.cg.shared.global [%0], [%1], 16;"
                 :: "r"(dst), "l"(src));
}

// mma.sync m16n8k16 row.col f32.f16.f16.f32 (accumulate in place)
__device__ __forceinline__ void hmma16816(float& d0, float& d1, float& d2, float& d3,
                                          unsigned a0, unsigned a1, unsigned a2, unsigned a3,
                                          unsigned b0, unsigned b1) {
    asm volatile(
        "mma.sync.aligned.m16n8k16.row.col.f32.f16.f16.f32 "
        "{%0,%1,%2,%3}, {%4,%5,%6,%7}, {%8,%9}, {%0,%1,%2,%3};"
        : "+f"(d0), "+f"(d1), "+f"(d2), "+f"(d3)
        : "r"(a0), "r"(a1), "r"(a2), "r"(a3), "r"(b0), "r"(b1));
}

// -------------------- merged prep kernel --------------------------------------
__global__ void prep_kernel(
    const float* __restrict__ Wxf, const float* __restrict__ Wxi,
    const float* __restrict__ Wxo, const float* __restrict__ Wxg,
    const float* __restrict__ Whf, const float* __restrict__ Whi,
    const float* __restrict__ Who, const float* __restrict__ Whg,
    const float* __restrict__ bxf, const float* __restrict__ bhf,
    const float* __restrict__ bxi, const float* __restrict__ bhi,
    const float* __restrict__ bxo, const float* __restrict__ bho,
    const float* __restrict__ bxg, const float* __restrict__ bhg)
{
    int idx = blockIdx.x * blockDim.x + threadIdx.x;

    if (idx < 8 * 16 * 16) g_flags[idx] = 0u;

    if (idx < G4) {
        int g = idx >> 9, jj = idx & 511;
        const float* bx = (g == 0) ? bxf : (g == 1) ? bxi : (g == 2) ? bxo : bxg;
        const float* bh = (g == 0) ? bhf : (g == 1) ? bhi : (g == 2) ? bho : bhg;
        g_bias[idx] = bx[jj] + bh[jj];
    }

    if (idx < G4 * IN_DIM) {         // g_WxT[n][k] = Wx_gate[k][unit] fp16
        int n = idx >> 8;
        int k = idx & 255;
        int g = n >> 9, unit = n & 511;
        const float* W = (g == 0) ? Wxf : (g == 1) ? Wxi : (g == 2) ? Wxo : Wxg;
        g_WxT[idx] = __float2half_rn(W[k * HID + unit]);
    }

    if (idx < G4 * HID) {
        int col = idx >> 9;
        int k   = idx & 511;
        int g   = col >> 9;
        int jj  = col & 511;
        const float* W = (g == 0) ? Whf : (g == 1) ? Whi : (g == 2) ? Who : Whg;
        g_WhT[idx] = W[k * HID + jj];   // WhT[col][k] = Wh[k][col]
    }
}

// -------------------- xproj via mma.sync (unchanged R12) -----------------------
__global__ __launch_bounds__(256, 2) void xproj_hmma(const float* __restrict__ x)
{
    extern __shared__ __half xs[];
    __half* a_hi = xs;                       // 2 x XA_BUF
    __half* a_lo = xs + 2 * XA_BUF;          // 2 x XA_BUF
    __half* bsm  = xs + 4 * XA_BUF;          // 2 x XB_BUF

    const int tid  = threadIdx.x;
    const int w    = tid >> 5;
    const int lane = tid & 31;
    const int g    = lane >> 2;
    const int tq   = lane & 3;
    const int mw   = w >> 2;                 // 0..1
    const int nw   = w & 3;                  // 0..3
    const int bm   = blockIdx.y * XM;
    const int bn   = blockIdx.x * XN;

    const int arow = tid >> 2;               // 0..63
    const int aq   = tid & 3;                // k-chunk of 8 floats
    const float* axp = x + (size_t)(bm + arow) * IN_DIM + aq * 8;

    const unsigned sb   = (unsigned)__cvta_generic_to_shared(xs);
    const unsigned bsmb = sb + (unsigned)(4 * XA_BUF) * 2u;

    float acc[2][4][4];
#pragma unroll
    for (int f = 0; f < 2; f++)
#pragma unroll
        for (int nf = 0; nf < 4; nf++)
#pragma unroll
            for (int q = 0; q < 4; q++) acc[f][nf][q] = 0.f;

#define CPB(p, ktg)                                                          \
    do {                                                                     \
        _Pragma("unroll")                                                    \
        for (int i = 0; i < 2; i++) {                                        \
            int idx = tid + (i << 8);                                        \
            int n   = idx >> 2;                                              \
            int ko  = (idx & 3) << 3;                                        \
            unsigned dst = bsmb + (unsigned)((p) * XB_BUF + n * XST + ko) * 2u; \
            cpasync16(dst, (const void*)(g_WxT + (size_t)(bn + n) * IN_DIM + (ktg) + ko)); \
        }                                                                    \
    } while (0)

#define STAGEA(p, v0, v1)                                                    \
    do {                                                                     \
        float ff[8] = {v0.x, v0.y, v0.z, v0.w, v1.x, v1.y, v1.z, v1.w};      \
        __align__(16) __half hh[8];                                          \
        __align__(16) __half hl[8];                                          \
        _Pragma("unroll")                                                    \
        for (int i = 0; i < 8; i++) {                                        \
            hh[i] = __float2half_rn(ff[i]);                                  \
            hl[i] = __float2half_rn(ff[i] - __half2float(hh[i]));            \
        }                                                                    \
        *(uint4*)(a_hi + (p) * XA_BUF + arow * XST + aq * 8) = *(uint4*)hh;  \
        *(uint4*)(a_lo + (p) * XA_BUF + arow * XST + aq * 8) = *(uint4*)hl;  \
    } while (0)

    // ---- prologue: tile 0 ----
    {
        CPB(0, 0);
        asm volatile("cp.async.commit_group;");
        float4 v0 = *(const float4*)(axp);
        float4 v1 = *(const float4*)(axp + 4);
        STAGEA(0, v0, v1);
        asm volatile("cp.async.wait_group 0;" ::: "memory");
    }
    __syncthreads();

#pragma unroll
    for (int kt = 0; kt < IN_DIM / XBK; kt++) {
        const int p = kt & 1;
        const bool has_next = (kt + 1) < (IN_DIM / XBK);

        float4 nv0, nv1;
        if (has_next) {
            CPB(p ^ 1, (kt + 1) * XBK);
            asm volatile("cp.async.commit_group;");
            nv0 = *(const float4*)(axp + (kt + 1) * XBK);
            nv1 = *(const float4*)(axp + (kt + 1) * XBK + 4);
        }

        const __half* ah_p = a_hi + p * XA_BUF;
        const __half* al_p = a_lo + p * XA_BUF;
        const __half* b_p  = bsm + p * XB_BUF;

#pragma unroll
        for (int ks = 0; ks < 2; ks++) {
            unsigned AH[2][4], AL[2][4], BB[4][2];
#pragma unroll
            for (int f = 0; f < 2; f++)
#pragma unroll
                for (int j = 0; j < 4; j++) {
                    int row = mw * 32 + f * 16 + g + ((j & 1) << 3);
                    int k   = ks * 16 + tq * 2 + ((j >> 1) << 3);
                    AH[f][j] = *(const unsigned*)(ah_p + row * XST + k);
                    AL[f][j] = *(const unsigned*)(al_p + row * XST + k);
                }
#pragma unroll
            for (int nf = 0; nf < 4; nf++) {
                int n = nw * 32 + nf * 8 + g;
                BB[nf][0] = *(const unsigned*)(b_p + n * XST + ks * 16 + tq * 2);
                BB[nf][1] = *(const unsigned*)(b_p + n * XST + ks * 16 + tq * 2 + 8);
            }
#pragma unroll
            for (int f = 0; f < 2; f++)
#pragma unroll
                for (int nf = 0; nf < 4; nf++) {
                    hmma16816(acc[f][nf][0], acc[f][nf][1], acc[f][nf][2], acc[f][nf][3],
                              AH[f][0], AH[f][1], AH[f][2], AH[f][3],
                              BB[nf][0], BB[nf][1]);
                    hmma16816(acc[f][nf][0], acc[f][nf][1], acc[f][nf][2], acc[f][nf][3],
                              AL[f][0], AL[f][1], AL[f][2], AL[f][3],
                              BB[nf][0], BB[nf][1]);
                }
        }

        if (has_next) {
            STAGEA(p ^ 1, nv0, nv1);
            asm volatile("cp.async.wait_group 0;" ::: "memory");
            __syncthreads();
        }
    }

    // ---- epilogue: bias add + store ----
#pragma unroll
    for (int nf = 0; nf < 4; nf++) {
        int col = bn + nw * 32 + nf * 8 + tq * 2;
        float b0 = g_bias[col];
        float b1 = g_bias[col + 1];
#pragma unroll
        for (int f = 0; f < 2; f++) {
            int r0 = bm + mw * 32 + f * 16 + g;
            float2 o0 = make_float2(acc[f][nf][0] + b0, acc[f][nf][1] + b1);
            float2 o1 = make_float2(acc[f][nf][2] + b0, acc[f][nf][3] + b1);
            *(float2*)&g_xp[(size_t)r0 * G4 + col]       = o0;
            *(float2*)&g_xp[(size_t)(r0 + 8) * G4 + col] = o1;
        }
    }
#undef CPB
#undef STAGEA
}

// -------------------- recurrence: mma.sync persistent --------------------------
// R16: 128 CTAs = 8 bg (8 batches) x 16 ug (32 units). 256 threads = 8 warps.
// Identical to R14 except the group barrier: distributed flags (st.release
// to own flag; threads 0..15 poll one flag each) -- no atomic serialization.
__global__ __launch_bounds__(256, 1) void lstm_rec_kernel(float* __restrict__ out)
{
    __shared__ __align__(16) __half b_hi[8 * BST];
    __shared__ __align__(16) __half b_lo[8 * BST];
    __shared__ float rg[128 * 9];

    const int tid  = threadIdx.x;
    const int w    = tid >> 5;
    const int lane = tid & 31;
    const int g    = lane >> 2;
    const int tq   = lane & 3;
    const int mt   = w;                 // 0..7 (rows mt*16..+15)
    const int cta  = blockIdx.x;
    const int ug   = cta & 15;          // units [ug*32, +32)
    const int bg   = cta >> 4;          // batches [bg*8, +8)

    // ---- Wh A-fragments (registers, once) ----
    unsigned ar[32][4];
#pragma unroll
    for (int ks = 0; ks < 32; ks++) {
#pragma unroll
        for (int j = 0; j < 4; j++) {
            int row  = mt * 16 + g + ((j & 1) << 3);     // 0..127
            int k    = ks * 16 + tq * 2 + ((j >> 1) << 3);
            int wcol = (row >> 5) * HID + (ug << 5) + (row & 31);
            float v0 = g_WhT[(size_t)wcol * HID + k];
            float v1 = g_WhT[(size_t)wcol * HID + k + 1];
            __half2 hv = __floats2half2_rn(v0, v1);
            ar[ks][j] = *(unsigned*)&hv;
        }
    }

    // B frag pointers: n-row = g (0..7)
    const __half* bhr = b_hi + g * BST + tq * 2;
    const __half* blr = b_lo + g * BST + tq * 2;

    const unsigned shi = (unsigned)__cvta_generic_to_shared(b_hi);
    const unsigned slo = (unsigned)__cvta_generic_to_shared(b_lo);

    // ---- activation mapping: (ab 0..7, au 0..31) ----
    const int ab = tid >> 5;
    const int au = tid & 31;
    const int gb = bg * 8 + ab;
    const int gj = (ug << 5) + au;

    unsigned int* myflag  = &g_flags[(bg * 16 + ug) * 16];
    unsigned int* pollbase = &g_flags[bg * 16 * 16];

    const size_t xof = (size_t)gb * G4 + gj;
    float c0 = g_xp[xof];
    float c1 = g_xp[xof + 512];
    float c2 = g_xp[xof + 1024];
    float c3 = g_xp[xof + 1536];

    float cval = 0.f;

    for (int t = 0; t < S_LEN; t++) {
        if (t > 0) {
            // ---- stage h(t-1) hi/lo: 8 rows x 512 halves each = 16KB ----
            const int pp = (t - 1) & 1;
            const __half* s_hi = g_hh[pp] + (size_t)(bg * 8) * HID;
            const __half* s_lo = g_hl[pp] + (size_t)(bg * 8) * HID;
#pragma unroll
            for (int i = 0; i < 4; i++) {          // 1024 16B-chunks / 256 thr
                int idx  = tid + (i << 8);
                int buf  = idx >> 9;               // 0: hi, 1: lo
                int rem  = idx & 511;
                int lrow = rem >> 6;
                int ch   = rem & 63;
                const __half* src = (buf ? s_lo : s_hi) + lrow * HID + (ch << 3);
                unsigned dst = (buf ? slo : shi)
                               + (unsigned)(lrow * BST + (ch << 3)) * 2u;
                cpasync16(dst, (const void*)src);
            }
            asm volatile("cp.async.commit_group;");
            asm volatile("cp.async.wait_group 0;" ::: "memory");
            __syncthreads();
        }

        // prefetch xp(t+1)
        float n0 = 0.f, n1 = 0.f, n2 = 0.f, n3 = 0.f;
        if (t + 1 < S_LEN) {
            size_t nb = (size_t)(t + 1) * BG + xof;
            n0 = g_xp[nb]; n1 = g_xp[nb + 512];
            n2 = g_xp[nb + 1024]; n3 = g_xp[nb + 1536];
        }

        if (t > 0) {
            float d0 = 0.f, d1 = 0.f, d2 = 0.f, d3 = 0.f;
#pragma unroll
            for (int ks = 0; ks < 32; ks++) {
                unsigned b0h = *(const unsigned*)(bhr + ks * 16);
                unsigned b1h = *(const unsigned*)(bhr + ks * 16 + 8);
                unsigned b0l = *(const unsigned*)(blr + ks * 16);
                unsigned b1l = *(const unsigned*)(blr + ks * 16 + 8);
                hmma16816(d0, d1, d2, d3,
                          ar[ks][0], ar[ks][1], ar[ks][2], ar[ks][3], b0h, b1h);
                hmma16816(d0, d1, d2, d3,
                          ar[ks][0], ar[ks][1], ar[ks][2], ar[ks][3], b0l, b1l);
            }
            int row = mt * 16 + g;
            int col = tq * 2;
            rg[row * 9 + col]           = d0;
            rg[row * 9 + col + 1]       = d1;
            rg[(row + 8) * 9 + col]     = d2;
            rg[(row + 8) * 9 + col + 1] = d3;
            __syncthreads();
        }

        // ---- activation: thread (ab, au) ----
        float gf = c0, gi = c1, go = c2, gg = c3;
        if (t > 0) {
            gf += rg[(au +  0) * 9 + ab];
            gi += rg[(au + 32) * 9 + ab];
            go += rg[(au + 64) * 9 + ab];
            gg += rg[(au + 96) * 9 + ab];
        }
        c0 = n0; c1 = n1; c2 = n2; c3 = n3;

        float fg = fast_sigmoid(gf);
        float ig = fast_sigmoid(gi);
        float og = fast_sigmoid(go);
        float gt = fast_tanh(gg);
        cval = fg * cval + ig * gt;
        float hval = og * fast_tanh(cval);

        out[(size_t)t * BH + (size_t)gb * HID + gj] = hval;
        {
            const int p = t & 1;
            __half hi = __float2half_rn(hval);
            __half lo = __float2half_rn(hval - __half2float(hi));
            g_hh[p][(size_t)gb * HID + gj] = hi;
            g_hl[p][(size_t)gb * HID + gj] = lo;
        }

        if (t < S_LEN - 1) {
            // ---- distributed-flag group barrier: 16 flags per bg ----
            __syncthreads();                 // all g_hh/g_hl stores issued
            if (tid == 0) {
                asm volatile("st.release.gpu.global.u32 [%0], %1;"
                             :: "l"(myflag), "r"((unsigned)(t + 1)) : "memory");
            }
            if (tid < 16) {
                unsigned target = (unsigned)(t + 1);
                unsigned v;
                const unsigned int* fp = pollbase + tid * 16;
                while (true) {
                    asm volatile("ld.acquire.gpu.global.u32 %0, [%1];"
                                 : "=r"(v) : "l"(fp) : "memory");
                    if (v >= target) break;
                    __nanosleep(20);
                }
            }
            __syncthreads();
        } else {
            out[(size_t)S_LEN * BH + (size_t)gb * HID + gj] = hval;        // h_f
            out[(size_t)S_LEN * BH + BH + (size_t)gb * HID + gj] = cval;   // c_f
        }
    }
}

// -------------------- launch ------------------------------------------------
extern "C" void kernel_launch(void* const* d_in, const int* in_sizes, int n_in,
                              void* d_out, int out_size)
{
    (void)in_sizes; (void)n_in; (void)out_size;
    const float* x   = (const float*)d_in[0];
    const float* Wxf = (const float*)d_in[1];
    const float* bxf = (const float*)d_in[2];
    const float* Whf = (const float*)d_in[3];
    const float* bhf = (const float*)d_in[4];
    const float* Wxi = (const float*)d_in[5];
    const float* bxi = (const float*)d_in[6];
    const float* Whi = (const float*)d_in[7];
    const float* bhi = (const float*)d_in[8];
    const float* Wxo = (const float*)d_in[9];
    const float* bxo = (const float*)d_in[10];
    const float* Who = (const float*)d_in[11];
    const float* bho = (const float*)d_in[12];
    const float* Wxg = (const float*)d_in[13];
    const float* bxg = (const float*)d_in[14];
    const float* Whg = (const float*)d_in[15];
    const float* bhg = (const float*)d_in[16];
    float* out = (float*)d_out;

    prep_kernel<<<(G4 * HID + 255) / 256, 256>>>(
        Wxf, Wxi, Wxo, Wxg, Whf, Whi, Who, Whg,
        bxf, bhf, bxi, bhi, bxo, bho, bxg, bhg);

    static bool attr_set = false;
    if (!attr_set) {
        cudaFuncSetAttribute(xproj_hmma,
                             cudaFuncAttributeMaxDynamicSharedMemorySize, XP_SMEM);
        attr_set = true;
    }
    dim3 gproj(G4 / XN, (S_LEN * BATCH) / XM);
    xproj_hmma<<<gproj, 256, XP_SMEM>>>(x);

    lstm_rec_kernel<<<NCTA, 256>>>(out);
}

// round 17
// speedup vs baseline: 1.7026x; 1.2112x over previous
#include <cuda_runtime.h>
#include <cuda_bf16.h>
#include <cuda_fp16.h>
#include <math.h>

// ---------------------------------------------------------------------------
// LSTM: S=512, B=64, I=256, H=512
// out = [h_seq (S,B,H) | h_final (B,H) | c_final (B,H)]  (fp32)
// xproj + recurrence both on mma.sync m16n8k16 (hi/lo fp16 splits ~ fp32).
// R17 = R14 (8bg x 16ug, red-counter barrier) + split staging: hi MMA
// overlaps the lo cp.async group.
// ---------------------------------------------------------------------------

#define S_LEN 512
#define BATCH 64
#define IN_DIM 256
#define HID 512
#define G4 2048              // 4*H
#define BH (BATCH*HID)       // 32768
#define BG (BATCH*G4)        // 131072
#define NCTA 128
#define BST 520              // rec B smem row stride (halves)

// xproj tiling: 64x128 CTA tile, warp tile 32x32, 2 CTAs/SM
#define XM 64
#define XN 128
#define XBK 32
#define XST 40               // xproj smem row stride (halves): 20 words/row
#define XA_BUF (XM*XST)      // 2560 halves per A buffer
#define XB_BUF (XN*XST)      // 5120 halves per B buffer
#define XP_SMEM ((4*XA_BUF + 2*XB_BUF) * 2)   // 40960 bytes

// -------------------- device scratch (static: no allocs allowed) ------------
__device__ float  g_xp[(size_t)S_LEN * BATCH * G4];  // x@Wx + bx + bh
__device__ __half g_WxT[(size_t)G4 * IN_DIM];        // WxT[n][k] fp16
__device__ float  g_WhT[(size_t)G4 * HID];           // WhT[col][k]
__device__ float  g_bias[G4];                        // bx + bh
__device__ __half g_hh[2][BH];                       // h hi fp16, ping-pong
__device__ __half g_hl[2][BH];                       // h lo fp16, ping-pong
__device__ unsigned int g_barc[8 * 16];              // per-bg counters, 64B apart

// fast activations
__device__ __forceinline__ float fast_exp(float x) {
    float e;
    asm("ex2.approx.f32 %0, %1;" : "=f"(e) : "f"(x * 1.4426950408889634f));
    return e;
}
__device__ __forceinline__ float fast_rcp(float x) {
    float r;
    asm("rcp.approx.f32 %0, %1;" : "=f"(r) : "f"(x));
    return r;
}
__device__ __forceinline__ float fast_sigmoid(float x) {
    return fast_rcp(1.f + fast_exp(-x));
}
__device__ __forceinline__ float fast_tanh(float x) {
    return 2.f * fast_rcp(1.f + fast_exp(-2.f * x)) - 1.f;
}

__device__ __forceinline__ void cpasync16(unsigned dst, const void* src) {
    asm volatile("cp.async.cg.shared.global [%0], [%1], 16;"
                 :: "r"(dst), "l"(src));
}

// mma.sync m16n8k16 row.col f32.f16.f16.f32 (accumulate in place)
__device__ __forceinline__ void hmma16816(float& d0, float& d1, float& d2, float& d3,
                                          unsigned a0, unsigned a1, unsigned a2, unsigned a3,
                                          unsigned b0, unsigned b1) {
    asm volatile(
        "mma.sync.aligned.m16n8k16.row.col.f32.f16.f16.f32 "
        "{%0,%1,%2,%3}, {%4,%5,%6,%7}, {%8,%9}, {%0,%1,%2,%3};"
        : "+f"(d0), "+f"(d1), "+f"(d2), "+f"(d3)
        : "r"(a0), "r"(a1), "r"(a2), "r"(a3), "r"(b0), "r"(b1));
}

// -------------------- merged prep kernel --------------------------------------
__global__ void prep_kernel(
    const float* __restrict__ Wxf, const float* __restrict__ Wxi,
    const float* __restrict__ Wxo, const float* __restrict__ Wxg,
    const float* __restrict__ Whf, const float* __restrict__ Whi,
    const float* __restrict__ Who, const float* __restrict__ Whg,
    const float* __restrict__ bxf, const float* __restrict__ bhf,
    const float* __restrict__ bxi, const float* __restrict__ bhi,
    const float* __restrict__ bxo, const float* __restrict__ bho,
    const float* __restrict__ bxg, const float* __restrict__ bhg)
{
    int idx = blockIdx.x * blockDim.x + threadIdx.x;

    if (idx < 8 * 16) g_barc[idx] = 0u;

    if (idx < G4) {
        int g = idx >> 9, jj = idx & 511;
        const float* bx = (g == 0) ? bxf : (g == 1) ? bxi : (g == 2) ? bxo : bxg;
        const float* bh = (g == 0) ? bhf : (g == 1) ? bhi : (g == 2) ? bho : bhg;
        g_bias[idx] = bx[jj] + bh[jj];
    }

    if (idx < G4 * IN_DIM) {         // g_WxT[n][k] = Wx_gate[k][unit] fp16
        int n = idx >> 8;
        int k = idx & 255;
        int g = n >> 9, unit = n & 511;
        const float* W = (g == 0) ? Wxf : (g == 1) ? Wxi : (g == 2) ? Wxo : Wxg;
        g_WxT[idx] = __float2half_rn(W[k * HID + unit]);
    }

    if (idx < G4 * HID) {
        int col = idx >> 9;
        int k   = idx & 511;
        int g   = col >> 9;
        int jj  = col & 511;
        const float* W = (g == 0) ? Whf : (g == 1) ? Whi : (g == 2) ? Who : Whg;
        g_WhT[idx] = W[k * HID + jj];   // WhT[col][k] = Wh[k][col]
    }
}

// -------------------- xproj via mma.sync (unchanged R12) -----------------------
__global__ __launch_bounds__(256, 2) void xproj_hmma(const float* __restrict__ x)
{
    extern __shared__ __half xs[];
    __half* a_hi = xs;                       // 2 x XA_BUF
    __half* a_lo = xs + 2 * XA_BUF;          // 2 x XA_BUF
    __half* bsm  = xs + 4 * XA_BUF;          // 2 x XB_BUF

    const int tid  = threadIdx.x;
    const int w    = tid >> 5;
    const int lane = tid & 31;
    const int g    = lane >> 2;
    const int tq   = lane & 3;
    const int mw   = w >> 2;                 // 0..1
    const int nw   = w & 3;                  // 0..3
    const int bm   = blockIdx.y * XM;
    const int bn   = blockIdx.x * XN;

    const int arow = tid >> 2;               // 0..63
    const int aq   = tid & 3;                // k-chunk of 8 floats
    const float* axp = x + (size_t)(bm + arow) * IN_DIM + aq * 8;

    const unsigned sb   = (unsigned)__cvta_generic_to_shared(xs);
    const unsigned bsmb = sb + (unsigned)(4 * XA_BUF) * 2u;

    float acc[2][4][4];
#pragma unroll
    for (int f = 0; f < 2; f++)
#pragma unroll
        for (int nf = 0; nf < 4; nf++)
#pragma unroll
            for (int q = 0; q < 4; q++) acc[f][nf][q] = 0.f;

#define CPB(p, ktg)                                                          \
    do {                                                                     \
        _Pragma("unroll")                                                    \
        for (int i = 0; i < 2; i++) {                                        \
            int idx = tid + (i << 8);                                        \
            int n   = idx >> 2;                                              \
            int ko  = (idx & 3) << 3;                                        \
            unsigned dst = bsmb + (unsigned)((p) * XB_BUF + n * XST + ko) * 2u; \
            cpasync16(dst, (const void*)(g_WxT + (size_t)(bn + n) * IN_DIM + (ktg) + ko)); \
        }                                                                    \
    } while (0)

#define STAGEA(p, v0, v1)                                                    \
    do {                                                                     \
        float ff[8] = {v0.x, v0.y, v0.z, v0.w, v1.x, v1.y, v1.z, v1.w};      \
        __align__(16) __half hh[8];                                          \
        __align__(16) __half hl[8];                                          \
        _Pragma("unroll")                                                    \
        for (int i = 0; i < 8; i++) {                                        \
            hh[i] = __float2half_rn(ff[i]);                                  \
            hl[i] = __float2half_rn(ff[i] - __half2float(hh[i]));            \
        }                                                                    \
        *(uint4*)(a_hi + (p) * XA_BUF + arow * XST + aq * 8) = *(uint4*)hh;  \
        *(uint4*)(a_lo + (p) * XA_BUF + arow * XST + aq * 8) = *(uint4*)hl;  \
    } while (0)

    // ---- prologue: tile 0 ----
    {
        CPB(0, 0);
        asm volatile("cp.async.commit_group;");
        float4 v0 = *(const float4*)(axp);
        float4 v1 = *(const float4*)(axp + 4);
        STAGEA(0, v0, v1);
        asm volatile("cp.async.wait_group 0;" ::: "memory");
    }
    __syncthreads();

#pragma unroll
    for (int kt = 0; kt < IN_DIM / XBK; kt++) {
        const int p = kt & 1;
        const bool has_next = (kt + 1) < (IN_DIM / XBK);

        float4 nv0, nv1;
        if (has_next) {
            CPB(p ^ 1, (kt + 1) * XBK);
            asm volatile("cp.async.commit_group;");
            nv0 = *(const float4*)(axp + (kt + 1) * XBK);
            nv1 = *(const float4*)(axp + (kt + 1) * XBK + 4);
        }

        const __half* ah_p = a_hi + p * XA_BUF;
        const __half* al_p = a_lo + p * XA_BUF;
        const __half* b_p  = bsm + p * XB_BUF;

#pragma unroll
        for (int ks = 0; ks < 2; ks++) {
            unsigned AH[2][4], AL[2][4], BB[4][2];
#pragma unroll
            for (int f = 0; f < 2; f++)
#pragma unroll
                for (int j = 0; j < 4; j++) {
                    int row = mw * 32 + f * 16 + g + ((j & 1) << 3);
                    int k   = ks * 16 + tq * 2 + ((j >> 1) << 3);
                    AH[f][j] = *(const unsigned*)(ah_p + row * XST + k);
                    AL[f][j] = *(const unsigned*)(al_p + row * XST + k);
                }
#pragma unroll
            for (int nf = 0; nf < 4; nf++) {
                int n = nw * 32 + nf * 8 + g;
                BB[nf][0] = *(const unsigned*)(b_p + n * XST + ks * 16 + tq * 2);
                BB[nf][1] = *(const unsigned*)(b_p + n * XST + ks * 16 + tq * 2 + 8);
            }
#pragma unroll
            for (int f = 0; f < 2; f++)
#pragma unroll
                for (int nf = 0; nf < 4; nf++) {
                    hmma16816(acc[f][nf][0], acc[f][nf][1], acc[f][nf][2], acc[f][nf][3],
                              AH[f][0], AH[f][1], AH[f][2], AH[f][3],
                              BB[nf][0], BB[nf][1]);
                    hmma16816(acc[f][nf][0], acc[f][nf][1], acc[f][nf][2], acc[f][nf][3],
                              AL[f][0], AL[f][1], AL[f][2], AL[f][3],
                              BB[nf][0], BB[nf][1]);
                }
        }

        if (has_next) {
            STAGEA(p ^ 1, nv0, nv1);
            asm volatile("cp.async.wait_group 0;" ::: "memory");
            __syncthreads();
        }
    }

    // ---- epilogue: bias add + store ----
#pragma unroll
    for (int nf = 0; nf < 4; nf++) {
        int col = bn + nw * 32 + nf * 8 + tq * 2;
        float b0 = g_bias[col];
        float b1 = g_bias[col + 1];
#pragma unroll
        for (int f = 0; f < 2; f++) {
            int r0 = bm + mw * 32 + f * 16 + g;
            float2 o0 = make_float2(acc[f][nf][0] + b0, acc[f][nf][1] + b1);
            float2 o1 = make_float2(acc[f][nf][2] + b0, acc[f][nf][3] + b1);
            *(float2*)&g_xp[(size_t)r0 * G4 + col]       = o0;
            *(float2*)&g_xp[(size_t)(r0 + 8) * G4 + col] = o1;
        }
    }
#undef CPB
#undef STAGEA
}

// -------------------- recurrence: mma.sync persistent --------------------------
// R17: 128 CTAs = 8 bg (8 batches) x 16 ug (32 units). 256 threads = 8 warps.
// Staging split: hi group committed first, lo second; hi MMA runs while the
// lo group is still in flight (wait_group 1 -> hi landed).
__global__ __launch_bounds__(256, 1) void lstm_rec_kernel(float* __restrict__ out)
{
    __shared__ __align__(16) __half b_hi[8 * BST];
    __shared__ __align__(16) __half b_lo[8 * BST];
    __shared__ float rg[128 * 9];

    const int tid  = threadIdx.x;
    const int w    = tid >> 5;
    const int lane = tid & 31;
    const int g    = lane >> 2;
    const int tq   = lane & 3;
    const int mt   = w;                 // 0..7 (rows mt*16..+15)
    const int cta  = blockIdx.x;
    const int ug   = cta & 15;          // units [ug*32, +32)
    const int bg   = cta >> 4;          // batches [bg*8, +8)

    // ---- Wh A-fragments (registers, once) ----
    unsigned ar[32][4];
#pragma unroll
    for (int ks = 0; ks < 32; ks++) {
#pragma unroll
        for (int j = 0; j < 4; j++) {
            int row  = mt * 16 + g + ((j & 1) << 3);     // 0..127
            int k    = ks * 16 + tq * 2 + ((j >> 1) << 3);
            int wcol = (row >> 5) * HID + (ug << 5) + (row & 31);
            float v0 = g_WhT[(size_t)wcol * HID + k];
            float v1 = g_WhT[(size_t)wcol * HID + k + 1];
            __half2 hv = __floats2half2_rn(v0, v1);
            ar[ks][j] = *(unsigned*)&hv;
        }
    }

    // B frag pointers: n-row = g (0..7)
    const __half* bhr = b_hi + g * BST + tq * 2;
    const __half* blr = b_lo + g * BST + tq * 2;

    const unsigned shi = (unsigned)__cvta_generic_to_shared(b_hi);
    const unsigned slo = (unsigned)__cvta_generic_to_shared(b_lo);

    // ---- activation mapping: (ab 0..7, au 0..31) ----
    const int ab = tid >> 5;
    const int au = tid & 31;
    const int gb = bg * 8 + ab;
    const int gj = (ug << 5) + au;

    unsigned int* barp = &g_barc[bg * 16];

    const size_t xof = (size_t)gb * G4 + gj;
    float c0 = g_xp[xof];
    float c1 = g_xp[xof + 512];
    float c2 = g_xp[xof + 1024];
    float c3 = g_xp[xof + 1536];

    float cval = 0.f;

    for (int t = 0; t < S_LEN; t++) {
        if (t > 0) {
            const int pp = (t - 1) & 1;
            const __half* s_hi = g_hh[pp] + (size_t)(bg * 8) * HID;
            const __half* s_lo = g_hl[pp] + (size_t)(bg * 8) * HID;
            // ---- group 1: hi (8KB) ----
#pragma unroll
            for (int i = 0; i < 2; i++) {          // 512 chunks / 256 thr
                int idx  = tid + (i << 8);
                int lrow = idx >> 6;
                int ch   = idx & 63;
                cpasync16(shi + (unsigned)(lrow * BST + (ch << 3)) * 2u,
                          (const void*)(s_hi + lrow * HID + (ch << 3)));
            }
            asm volatile("cp.async.commit_group;");
            // ---- group 2: lo (8KB) ----
#pragma unroll
            for (int i = 0; i < 2; i++) {
                int idx  = tid + (i << 8);
                int lrow = idx >> 6;
                int ch   = idx & 63;
                cpasync16(slo + (unsigned)(lrow * BST + (ch << 3)) * 2u,
                          (const void*)(s_lo + lrow * HID + (ch << 3)));
            }
            asm volatile("cp.async.commit_group;");
            asm volatile("cp.async.wait_group 1;" ::: "memory");   // hi landed
            __syncthreads();
        }

        // prefetch xp(t+1)
        float n0 = 0.f, n1 = 0.f, n2 = 0.f, n3 = 0.f;
        if (t + 1 < S_LEN) {
            size_t nb = (size_t)(t + 1) * BG + xof;
            n0 = g_xp[nb]; n1 = g_xp[nb + 512];
            n2 = g_xp[nb + 1024]; n3 = g_xp[nb + 1536];
        }

        if (t > 0) {
            float d0 = 0.f, d1 = 0.f, d2 = 0.f, d3 = 0.f;
            // ---- hi MMA (lo group still in flight) ----
#pragma unroll
            for (int ks = 0; ks < 32; ks++) {
                unsigned b0h = *(const unsigned*)(bhr + ks * 16);
                unsigned b1h = *(const unsigned*)(bhr + ks * 16 + 8);
                hmma16816(d0, d1, d2, d3,
                          ar[ks][0], ar[ks][1], ar[ks][2], ar[ks][3], b0h, b1h);
            }
            // ---- wait lo, then lo MMA ----
            asm volatile("cp.async.wait_group 0;" ::: "memory");
            __syncthreads();
#pragma unroll
            for (int ks = 0; ks < 32; ks++) {
                unsigned b0l = *(const unsigned*)(blr + ks * 16);
                unsigned b1l = *(const unsigned*)(blr + ks * 16 + 8);
                hmma16816(d0, d1, d2, d3,
                          ar[ks][0], ar[ks][1], ar[ks][2], ar[ks][3], b0l, b1l);
            }
            int row = mt * 16 + g;
            int col = tq * 2;
            rg[row * 9 + col]           = d0;
            rg[row * 9 + col + 1]       = d1;
            rg[(row + 8) * 9 + col]     = d2;
            rg[(row + 8) * 9 + col + 1] = d3;
            __syncthreads();
        }

        // ---- activation: thread (ab, au) ----
        float gf = c0, gi = c1, go = c2, gg = c3;
        if (t > 0) {
            gf += rg[(au +  0) * 9 + ab];
            gi += rg[(au + 32) * 9 + ab];
            go += rg[(au + 64) * 9 + ab];
            gg += rg[(au + 96) * 9 + ab];
        }
        c0 = n0; c1 = n1; c2 = n2; c3 = n3;

        float fg = fast_sigmoid(gf);
        float ig = fast_sigmoid(gi);
        float og = fast_sigmoid(go);
        float gt = fast_tanh(gg);
        cval = fg * cval + ig * gt;
        float hval = og * fast_tanh(cval);

        out[(size_t)t * BH + (size_t)gb * HID + gj] = hval;
        {
            const int p = t & 1;
            __half hi = __float2half_rn(hval);
            __half lo = __float2half_rn(hval - __half2float(hi));
            g_hh[p][(size_t)gb * HID + gj] = hi;
            g_hl[p][(size_t)gb * HID + gj] = lo;
        }

        if (t < S_LEN - 1) {
            // ---- per-bg barrier: 16 arrivals on one counter ----
            __syncthreads();
            if (tid == 0) {
                asm volatile("red.release.gpu.global.add.u32 [%0], 1;"
                             :: "l"(barp) : "memory");
                unsigned target = (unsigned)(t + 1) * 16u;
                unsigned v;
                while (true) {
                    asm volatile("ld.acquire.gpu.global.u32 %0, [%1];"
                                 : "=r"(v) : "l"(barp) : "memory");
                    if (v >= target) break;
                    __nanosleep(20);
                }
            }
            __syncthreads();
        } else {
            out[(size_t)S_LEN * BH + (size_t)gb * HID + gj] = hval;        // h_f
            out[(size_t)S_LEN * BH + BH + (size_t)gb * HID + gj] = cval;   // c_f
        }
    }
}

// -------------------- launch ------------------------------------------------
extern "C" void kernel_launch(void* const* d_in, const int* in_sizes, int n_in,
                              void* d_out, int out_size)
{
    (void)in_sizes; (void)n_in; (void)out_size;
    const float* x   = (const float*)d_in[0];
    const float* Wxf = (const float*)d_in[1];
    const float* bxf = (const float*)d_in[2];
    const float* Whf = (const float*)d_in[3];
    const float* bhf = (const float*)d_in[4];
    const float* Wxi = (const float*)d_in[5];
    const float* bxi = (const float*)d_in[6];
    const float* Whi = (const float*)d_in[7];
    const float* bhi = (const float*)d_in[8];
    const float* Wxo = (const float*)d_in[9];
    const float* bxo = (const float*)d_in[10];
    const float* Who = (const float*)d_in[11];
    const float* bho = (const float*)d_in[12];
    const float* Wxg = (const float*)d_in[13];
    const float* bxg = (const float*)d_in[14];
    const float* Whg = (const float*)d_in[15];
    const float* bhg = (const float*)d_in[16];
    float* out = (float*)d_out;

    prep_kernel<<<(G4 * HID + 255) / 256, 256>>>(
        Wxf, Wxi, Wxo, Wxg, Whf, Whi, Who, Whg,
        bxf, bhf, bxi, bhi, bxo, bho, bxg, bhg);

    static bool attr_set = false;
    if (!attr_set) {
        cudaFuncSetAttribute(xproj_hmma,
                             cudaFuncAttributeMaxDynamicSharedMemorySize, XP_SMEM);
        attr_set = true;
    }
    dim3 gproj(G4 / XN, (S_LEN * BATCH) / XM);
    xproj_hmma<<<gproj, 256, XP_SMEM>>>(x);

    lstm_rec_kernel<<<NCTA, 256>>>(out);
}